// round 7
// baseline (speedup 1.0000x reference)
#include <cuda_runtime.h>
#include <stdint.h>

#define NN 100000
#define EE 1600000
#define DD 32
#define KTOP 1024
#define HBITS 17
#define HSIZE (1 << HBITS)
#define CAP 4096
#define SCAN_B 98   // ceil(NN / 1024)

// ---------------- scratch (device globals; no allocation allowed) ----------------
__device__ int    g_rowcnt[NN];
__device__ int    g_rowptr[NN + 1];
__device__ int    g_cursor[NN];
__device__ int    g_perm[EE];
__device__ float2 g_cv[EE];                       // (col bits, current val) — updated in steps
__device__ float  g_e0[NN * DD], g_e1[NN * DD], g_e2[NN * DD], g_e3[NN * DD];
__device__ float  g_n0[NN], g_n1[NN], g_n2[NN], g_n3[NN];
__device__ float  g_order[NN];
__device__ float  g_scores[NN];
__device__ int    g_hist[HSIZE];
__device__ int    g_blockTot[SCAN_B], g_blockOff[SCAN_B];
__device__ int    g_sel_digit;
__device__ int    g_cand_cnt;
__device__ unsigned int g_cand_key[CAP];
__device__ int    g_cand_idx[CAP];

// ---------------- threefry2x32 (JAX-compatible, partitionable mode) ----------------
__host__ __device__ __forceinline__ void tf2x32(uint32_t k0, uint32_t k1,
                                                uint32_t x0, uint32_t x1,
                                                uint32_t &o0, uint32_t &o1) {
    uint32_t ks2 = k0 ^ k1 ^ 0x1BD11BDAu;
    x0 += k0; x1 += k1;
#define TFR(r) do { x0 += x1; x1 = (x1 << (r)) | (x1 >> (32 - (r))); x1 ^= x0; } while (0)
    TFR(13); TFR(15); TFR(26); TFR(6);
    x0 += k1;  x1 += ks2 + 1u;
    TFR(17); TFR(29); TFR(16); TFR(24);
    x0 += ks2; x1 += k0 + 2u;
    TFR(13); TFR(15); TFR(26); TFR(6);
    x0 += k0;  x1 += k1 + 3u;
    TFR(17); TFR(29); TFR(16); TFR(24);
    x0 += k1;  x1 += ks2 + 4u;
    TFR(13); TFR(15); TFR(26); TFR(6);
    x0 += ks2; x1 += k0 + 5u;
#undef TFR
    o0 = x0; o1 = x1;
}

__device__ __forceinline__ uint32_t rbits32(uint32_t k0, uint32_t k1, uint32_t i) {
    uint32_t a, b;
    tf2x32(k0, k1, 0u, i, a, b);
    return a ^ b;
}

__device__ __forceinline__ float u01(uint32_t bits) {
    return __uint_as_float((bits >> 9) | 0x3f800000u) - 1.0f;
}

__device__ __forceinline__ uint32_t score_key(float f) {
    uint32_t b = __float_as_uint(f);
    return (b & 0x80000000u) ? ~b : (b | 0x80000000u);
}

// ---------------- init ----------------
__global__ void zero_kernel() {
    int i = blockIdx.x * blockDim.x + threadIdx.x;
    if (i < HSIZE) g_hist[i] = 0;
    if (i < NN) g_rowcnt[i] = 0;
    if (i == 0) g_cand_cnt = 0;
}

__global__ void rowcnt_kernel(const int* __restrict__ rows) {
    int e = blockIdx.x * blockDim.x + threadIdx.x;
    if (e >= EE) return;
    atomicAdd(&g_rowcnt[rows[e]], 1);
}

// ---------------- 3-phase exclusive scan of rowcnt -> rowptr ----------------
__global__ void scan1_kernel() {           // SCAN_B blocks x 1024
    __shared__ int sm[1024];
    int t = threadIdx.x, b = blockIdx.x, i = b * 1024 + t;
    int x = (i < NN) ? g_rowcnt[i] : 0;
    sm[t] = x;
    __syncthreads();
    for (int off = 1; off < 1024; off <<= 1) {
        int y = (t >= off) ? sm[t - off] : 0;
        __syncthreads();
        sm[t] += y;
        __syncthreads();
    }
    if (i < NN) g_rowptr[i] = sm[t] - x;   // local exclusive
    if (t == 1023) g_blockTot[b] = sm[t];
}

__global__ void scan2_kernel() {           // 1 block x 128, parallel scan of block totals
    __shared__ int sm[128];
    int t = threadIdx.x;
    int x = (t < SCAN_B) ? g_blockTot[t] : 0;
    sm[t] = x;
    __syncthreads();
    for (int off = 1; off < 128; off <<= 1) {
        int y = (t >= off) ? sm[t - off] : 0;
        __syncthreads();
        sm[t] += y;
        __syncthreads();
    }
    if (t < SCAN_B) g_blockOff[t] = sm[t] - x;   // exclusive
    if (t == SCAN_B - 1) g_rowptr[NN] = sm[t];
}

__global__ void scan3_kernel() {           // add offsets, init cursor
    int t = threadIdx.x, b = blockIdx.x, i = b * 1024 + t;
    if (i < NN) {
        int v = g_rowptr[i] + g_blockOff[b];
        g_rowptr[i] = v;
        g_cursor[i] = v;
    }
}

__global__ void scatter_kernel(const int* __restrict__ rows) {
    int e = blockIdx.x * blockDim.x + threadIdx.x;
    if (e >= EE) return;
    int pos = atomicAdd(&g_cursor[rows[e]], 1);
    g_perm[pos] = e;
}

// Warp-per-row sort of edge ids (deterministic accumulation order).
__global__ void warpsort_kernel() {
    int gid = blockIdx.x * blockDim.x + threadIdx.x;
    int r = gid >> 5;
    int lane = threadIdx.x & 31;
    if (r >= NN) return;
    int s = g_rowptr[r], e = g_rowptr[r + 1];
    int deg = e - s;
    if (deg <= 1) return;
    if (deg <= 32) {
        int v = (lane < deg) ? g_perm[s + lane] : 0x7fffffff;
#pragma unroll
        for (int k = 2; k <= 32; k <<= 1) {
#pragma unroll
            for (int j = k >> 1; j > 0; j >>= 1) {
                int o = __shfl_xor_sync(0xffffffffu, v, j);
                bool dir = ((lane & k) == 0);
                bool lower = ((lane & j) == 0);
                int mn = min(v, o), mx = max(v, o);
                v = (dir == lower) ? mn : mx;
            }
        }
        if (lane < deg) g_perm[s + lane] = v;
    } else if (lane == 0) {
        for (int i = s + 1; i < e; i++) {
            int v = g_perm[i];
            int j = i - 1;
            while (j >= s && g_perm[j] > v) { g_perm[j + 1] = g_perm[j]; j--; }
            g_perm[j + 1] = v;
        }
    }
}

// ---------------- pack (col, adj) into CSR order — no hashing here ----------------
__global__ void pack_kernel(const int* __restrict__ cols, const float* __restrict__ adj) {
    int j = blockIdx.x * blockDim.x + threadIdx.x;
    if (j >= EE) return;
    int e = g_perm[j];
    g_cv[j] = make_float2(__int_as_float(cols[e]), adj[e]);
}

// ---------------- fused propagation step ----------------
// Warp per row, lane = dim. Edges processed in chunks of 32: lane i owns edge
// base+i for the coalesced cv/num/perm loads and (for STEP<3) computes that
// edge's dropout mask (threefry, key fk[STEP]) and writes the compounded value
// back to g_cv for the next step. Inner broadcast loop shfls (col,val) while
// all 32 lanes gather one embedding row.
template <int STEP>
__global__ void step_kernel(const float* __restrict__ embeds,
                            uint32_t k0, uint32_t k1, float keep_prob) {
    int gid = blockIdx.x * blockDim.x + threadIdx.x;
    int r = gid >> 5;
    int lane = threadIdx.x & 31;
    if (r >= NN) return;

    const float* __restrict__ emb_cur =
        (STEP == 0) ? embeds : (STEP == 1) ? g_e0 : (STEP == 2) ? g_e1 : g_e2;
    float* __restrict__ emb_next =
        (STEP == 0) ? g_e0 : (STEP == 1) ? g_e1 : (STEP == 2) ? g_e2 : g_e3;
    const float* __restrict__ num_cur =
        (STEP == 1) ? g_n0 : (STEP == 2) ? g_n1 : g_n2;
    float* __restrict__ num_next =
        (STEP == 0) ? g_n0 : (STEP == 1) ? g_n1 : (STEP == 2) ? g_n2 : g_n3;

    int s = g_rowptr[r], e = g_rowptr[r + 1];
    float acc = 0.f, accn_l = 0.f, acco_l = 0.f;

    for (int base = s; base < e; base += 32) {
        int j = base + lane;
        bool valid = j < e;
        float2 c2 = valid ? g_cv[j] : make_float2(__int_as_float(0), 0.f);
        int   c = __float_as_int(c2.x);
        float v = c2.y;
        if (STEP > 0) {
            float nv = valid ? __ldg(&num_cur[c]) : 0.f;
            accn_l += v * nv;
        }
        if (STEP < 3) {
            acco_l += v;            // STEP==3: order is dead after the last step
            if (valid) {
                int eid = g_perm[j];
                float m = floorf(u01(rbits32(k0, k1, (uint32_t)eid)) + keep_prob);
                g_cv[j] = make_float2(c2.x, v * m);
            }
        }
        int cnt = min(32, e - base);
        for (int t = 0; t < cnt; t++) {
            int   cc = __shfl_sync(0xffffffffu, c, t);
            float vv = __shfl_sync(0xffffffffu, v, t);
            acc += vv * __ldg(&emb_cur[cc * DD + lane]);
        }
    }
#pragma unroll
    for (int o = 16; o; o >>= 1) {
        if (STEP < 3) acco_l += __shfl_xor_sync(0xffffffffu, acco_l, o);
        if (STEP > 0) accn_l += __shfl_xor_sync(0xffffffffu, accn_l, o);
    }

    float ec = emb_cur[r * DD + lane];
    if (STEP == 0) {
        emb_next[r * DD + lane] = acc - ec;
        if (lane == 0) { num_next[r] = acco_l; g_order[r] = acco_l; }
    } else {
        float od = g_order[r];
        emb_next[r * DD + lane] = acc - ec - od * ec;
        if (lane == 0) {
            num_next[r] = accn_l - num_cur[r] - od;
            if (STEP < 3) g_order[r] = acco_l;
        }
    }
}

// ---------------- scoring (sum + normalize + dot + Gumbel) with fused histogram ----------------
__global__ void score_kernel(const float* __restrict__ embeds, float* __restrict__ out,
                             int n_score_out) {
    int gid = blockIdx.x * blockDim.x + threadIdx.x;
    int i = gid >> 5;
    int lane = threadIdx.x & 31;
    if (i >= NN) return;

    int idx = i * DD + lane;
    float esum = g_e0[idx] + g_e1[idx] + g_e2[idx] + g_e3[idx];
    float ns = g_n0[i] + g_n1[i] + g_n2[i] + g_n3[i] + 1e-8f;
    float sub = esum / ns;
    float em = embeds[idx];
    float ss = sub * sub, ee = em * em;
#pragma unroll
    for (int o = 16; o; o >>= 1) {
        ss += __shfl_xor_sync(0xffffffffu, ss, o);
        ee += __shfl_xor_sync(0xffffffffu, ee, o);
    }
    float a = sub / fmaxf(sqrtf(ss), 1e-12f);
    float b = em / fmaxf(sqrtf(ee), 1e-12f);
    float d = a * b;
#pragma unroll
    for (int o = 16; o; o >>= 1) d += __shfl_xor_sync(0xffffffffu, d, o);

    if (lane == 0) {
        float u = u01(rbits32(0u, 7u, (uint32_t)i));   // key(7)
        float sc = d + (-logf(-logf(u)));
        g_scores[i] = sc;
        if (i < n_score_out) out[i] = sc;
        atomicAdd(&g_hist[score_key(sc) >> (32 - HBITS)], 1);
    }
}

// ---------------- top-k: threshold + compact + bitonic ----------------
__global__ void thresh_kernel() {   // 1 block, 1024 threads
    __shared__ int part[1024];
    const int T = 1024, CH = HSIZE / 1024;   // 128
    int t = threadIdx.x;
    int s = t * CH;
    int sum = 0;
    for (int i = 0; i < CH; i++) sum += g_hist[s + i];
    part[t] = sum;
    __syncthreads();
    if (t == 0) {
        int cum = 0, d = 0;
        for (int tt = T - 1; tt >= 0; tt--) {
            if (cum + part[tt] >= KTOP) {
                for (int b = tt * CH + CH - 1; b >= tt * CH; b--) {
                    int h = g_hist[b];
                    if (cum + h >= KTOP) { d = b; break; }
                    cum += h;
                }
                break;
            }
            cum += part[tt];
        }
        g_sel_digit = d;
    }
}

__global__ void compact_kernel() {
    int i = blockIdx.x * blockDim.x + threadIdx.x;
    if (i >= NN) return;
    uint32_t k = score_key(g_scores[i]);
    if ((int)(k >> (32 - HBITS)) >= g_sel_digit) {
        int p = atomicAdd(&g_cand_cnt, 1);
        if (p < CAP) { g_cand_key[p] = k; g_cand_idx[p] = i; }
    }
}

__global__ void final_kernel(float* __restrict__ out, int out_size) {  // 1 block, 1024 thr
    __shared__ unsigned long long sm[CAP];
    int n = g_cand_cnt; if (n > CAP) n = CAP;
    int m = KTOP; while (m < n) m <<= 1;      // power-of-2 sort size (usually 2048)
    for (int i = threadIdx.x; i < m; i += blockDim.x) {
        sm[i] = (i < n)
            ? ((((unsigned long long)g_cand_key[i]) << 32) | (uint32_t)(~(uint32_t)g_cand_idx[i]))
            : 0ull;
    }
    __syncthreads();
    for (int size = 2; size <= m; size <<= 1) {
        for (int stride = size >> 1; stride > 0; stride >>= 1) {
            for (int i = threadIdx.x; i < m / 2; i += blockDim.x) {
                int lo = 2 * i - (i & (stride - 1));
                int hi = lo + stride;
                bool desc = ((lo & size) == 0);
                unsigned long long a = sm[lo], b = sm[hi];
                bool sw = desc ? (a < b) : (a > b);
                if (sw) { sm[lo] = b; sm[hi] = a; }
            }
            __syncthreads();
        }
    }
    for (int j = threadIdx.x; j < KTOP; j += blockDim.x) {
        uint32_t idx = ~(uint32_t)(sm[j] & 0xffffffffull);
        if (out_size >= NN + KTOP) out[NN + j] = (float)idx;
        else if (out_size == KTOP) ((int*)out)[j] = (int)idx;
    }
}

// ---------------- launch ----------------
extern "C" void kernel_launch(void* const* d_in, const int* in_sizes, int n_in,
                              void* d_out, int out_size) {
    const int* rows = (const int*)d_in[0];       // edge_index[0]
    const int* cols = rows + EE;                 // edge_index[1]
    const float* adj = (const float*)d_in[1];
    const float* embeds = (const float*)d_in[2];
    float* out = (float*)d_out;
    (void)in_sizes; (void)n_in;

    // fold_in(key(42), i): threefry((0,42),(0,i)) -> derived key
    uint32_t fk[3][2];
    for (uint32_t i = 0; i < 3; i++) tf2x32(0u, 42u, 0u, i, fk[i][0], fk[i][1]);

    const int tb = 256;
    zero_kernel<<<(HSIZE + tb - 1) / tb, tb>>>();
    rowcnt_kernel<<<(EE + tb - 1) / tb, tb>>>(rows);
    scan1_kernel<<<SCAN_B, 1024>>>();
    scan2_kernel<<<1, 128>>>();
    scan3_kernel<<<SCAN_B, 1024>>>();
    scatter_kernel<<<(EE + tb - 1) / tb, tb>>>(rows);
    warpsort_kernel<<<(NN * 32 + tb - 1) / tb, tb>>>();
    pack_kernel<<<(EE + tb - 1) / tb, tb>>>(cols, adj);

    step_kernel<0><<<(NN * 32 + tb - 1) / tb, tb>>>(embeds, fk[0][0], fk[0][1], 0.5f);
    step_kernel<1><<<(NN * 32 + tb - 1) / tb, tb>>>(embeds, fk[1][0], fk[1][1], 0.25f);
    step_kernel<2><<<(NN * 32 + tb - 1) / tb, tb>>>(embeds, fk[2][0], fk[2][1], 0.125f);
    step_kernel<3><<<(NN * 32 + tb - 1) / tb, tb>>>(embeds, 0u, 0u, 0.f);

    int n_score_out = (out_size == KTOP) ? 0 : ((out_size < NN) ? out_size : NN);
    score_kernel<<<(NN * 32 + tb - 1) / tb, tb>>>(embeds, out, n_score_out);

    thresh_kernel<<<1, 1024>>>();
    compact_kernel<<<(NN + tb - 1) / tb, tb>>>();
    final_kernel<<<1, 1024>>>(out, out_size);
}

// round 10
// speedup vs baseline: 1.1480x; 1.1480x over previous
#include <cuda_runtime.h>
#include <stdint.h>

#define NN 100000
#define EE 1600000
#define DD 32
#define KTOP 1024
#define HBITS 17
#define HSIZE (1 << HBITS)
#define CAP 4096
#define SCAN_B 98   // ceil(NN / 1024)

// ---------------- scratch (device globals; no allocation allowed) ----------------
__device__ int    g_rowcnt[NN];
__device__ int    g_rowptr[NN + 1];
__device__ int    g_cursor[NN];
__device__ int    g_perm[EE];
__device__ int4   g_cve[EE];                      // (col, val bits, eid, pad)
__device__ float  g_e0[NN * DD], g_e1[NN * DD], g_e2[NN * DD], g_e3[NN * DD];
__device__ float  g_n0[NN], g_n1[NN], g_n2[NN], g_n3[NN];
__device__ float  g_order[NN];
__device__ float  g_scores[NN];
__device__ int    g_hist[HSIZE];
__device__ int    g_blockTot[SCAN_B], g_blockOff[SCAN_B];
__device__ int    g_sel_digit;
__device__ int    g_cand_cnt;
__device__ unsigned int g_cand_key[CAP];
__device__ int    g_cand_idx[CAP];

// ---------------- threefry2x32 (JAX-compatible, partitionable mode) ----------------
__host__ __device__ __forceinline__ void tf2x32(uint32_t k0, uint32_t k1,
                                                uint32_t x0, uint32_t x1,
                                                uint32_t &o0, uint32_t &o1) {
    uint32_t ks2 = k0 ^ k1 ^ 0x1BD11BDAu;
    x0 += k0; x1 += k1;
#define TFR(r) do { x0 += x1; x1 = (x1 << (r)) | (x1 >> (32 - (r))); x1 ^= x0; } while (0)
    TFR(13); TFR(15); TFR(26); TFR(6);
    x0 += k1;  x1 += ks2 + 1u;
    TFR(17); TFR(29); TFR(16); TFR(24);
    x0 += ks2; x1 += k0 + 2u;
    TFR(13); TFR(15); TFR(26); TFR(6);
    x0 += k0;  x1 += k1 + 3u;
    TFR(17); TFR(29); TFR(16); TFR(24);
    x0 += k1;  x1 += ks2 + 4u;
    TFR(13); TFR(15); TFR(26); TFR(6);
    x0 += ks2; x1 += k0 + 5u;
#undef TFR
    o0 = x0; o1 = x1;
}

__device__ __forceinline__ uint32_t rbits32(uint32_t k0, uint32_t k1, uint32_t i) {
    uint32_t a, b;
    tf2x32(k0, k1, 0u, i, a, b);
    return a ^ b;
}

__device__ __forceinline__ float u01(uint32_t bits) {
    return __uint_as_float((bits >> 9) | 0x3f800000u) - 1.0f;
}

__device__ __forceinline__ uint32_t score_key(float f) {
    uint32_t b = __float_as_uint(f);
    return (b & 0x80000000u) ? ~b : (b | 0x80000000u);
}

// ---------------- init ----------------
__global__ void zero_kernel() {
    int i = blockIdx.x * blockDim.x + threadIdx.x;
    if (i < HSIZE) g_hist[i] = 0;
    if (i < NN) g_rowcnt[i] = 0;
    if (i == 0) g_cand_cnt = 0;
}

__global__ void rowcnt_kernel(const int* __restrict__ rows) {
    int e = blockIdx.x * blockDim.x + threadIdx.x;
    if (e >= EE) return;
    atomicAdd(&g_rowcnt[rows[e]], 1);
}

// ---------------- 3-phase exclusive scan of rowcnt -> rowptr ----------------
__global__ void scan1_kernel() {           // SCAN_B blocks x 1024
    __shared__ int sm[1024];
    int t = threadIdx.x, b = blockIdx.x, i = b * 1024 + t;
    int x = (i < NN) ? g_rowcnt[i] : 0;
    sm[t] = x;
    __syncthreads();
    for (int off = 1; off < 1024; off <<= 1) {
        int y = (t >= off) ? sm[t - off] : 0;
        __syncthreads();
        sm[t] += y;
        __syncthreads();
    }
    if (i < NN) g_rowptr[i] = sm[t] - x;   // local exclusive
    if (t == 1023) g_blockTot[b] = sm[t];
}

__global__ void scan2_kernel() {           // 1 block x 128
    __shared__ int sm[128];
    int t = threadIdx.x;
    int x = (t < SCAN_B) ? g_blockTot[t] : 0;
    sm[t] = x;
    __syncthreads();
    for (int off = 1; off < 128; off <<= 1) {
        int y = (t >= off) ? sm[t - off] : 0;
        __syncthreads();
        sm[t] += y;
        __syncthreads();
    }
    if (t < SCAN_B) g_blockOff[t] = sm[t] - x;   // exclusive
    if (t == SCAN_B - 1) g_rowptr[NN] = sm[t];
}

__global__ void scan3_kernel() {           // add offsets, init cursor
    int t = threadIdx.x, b = blockIdx.x, i = b * 1024 + t;
    if (i < NN) {
        int v = g_rowptr[i] + g_blockOff[b];
        g_rowptr[i] = v;
        g_cursor[i] = v;
    }
}

__global__ void scatter_kernel(const int* __restrict__ rows) {
    int e = blockIdx.x * blockDim.x + threadIdx.x;
    if (e >= EE) return;
    int pos = atomicAdd(&g_cursor[rows[e]], 1);
    g_perm[pos] = e;
}

// Warp-per-row: sort edge ids (deterministic order), then gather (col, adj)
// and write the packed int4 CSR edge array directly from registers.
__global__ void warpsort_pack_kernel(const int* __restrict__ cols,
                                     const float* __restrict__ adj) {
    int gid = blockIdx.x * blockDim.x + threadIdx.x;
    int r = gid >> 5;
    int lane = threadIdx.x & 31;
    if (r >= NN) return;
    int s = g_rowptr[r], e = g_rowptr[r + 1];
    int deg = e - s;
    if (deg == 0) return;
    if (deg <= 32) {
        int v = (lane < deg) ? g_perm[s + lane] : 0x7fffffff;
#pragma unroll
        for (int k = 2; k <= 32; k <<= 1) {
#pragma unroll
            for (int j = k >> 1; j > 0; j >>= 1) {
                int o = __shfl_xor_sync(0xffffffffu, v, j);
                bool dir = ((lane & k) == 0);
                bool lower = ((lane & j) == 0);
                int mn = min(v, o), mx = max(v, o);
                v = (dir == lower) ? mn : mx;
            }
        }
        if (lane < deg) {
            int   c = __ldg(&cols[v]);
            float a = __ldg(&adj[v]);
            g_cve[s + lane] = make_int4(c, __float_as_int(a), v, 0);
        }
    } else {
        if (lane == 0) {
            for (int i = s + 1; i < e; i++) {
                int v = g_perm[i];
                int j = i - 1;
                while (j >= s && g_perm[j] > v) { g_perm[j + 1] = g_perm[j]; j--; }
                g_perm[j + 1] = v;
            }
        }
        __syncwarp();
        for (int j = s + lane; j < e; j += 32) {
            int eid = g_perm[j];
            g_cve[j] = make_int4(__ldg(&cols[eid]), __float_as_int(__ldg(&adj[eid])), eid, 0);
        }
    }
}

// ---------------- fused propagation step ----------------
// Warp per row, lane = dim. Chunks of 32 edges: lane i owns edge base+i
// (coalesced int4 load). Nonzero-val lanes are compacted with ballot/__fns,
// then a quad-unrolled broadcast loop (MLP=4) gathers embedding rows.
// For STEP<3, lanes with v!=0 compute the threefry dropout mask for their
// edge and store the compounded value (next step's val) back to g_cve.
template <int STEP>
__global__ void step_kernel(const float* __restrict__ embeds,
                            uint32_t k0, uint32_t k1, float keep_prob) {
    int gid = blockIdx.x * blockDim.x + threadIdx.x;
    int r = gid >> 5;
    int lane = threadIdx.x & 31;
    if (r >= NN) return;

    const float* __restrict__ emb_cur =
        (STEP == 0) ? embeds : (STEP == 1) ? g_e0 : (STEP == 2) ? g_e1 : g_e2;
    float* __restrict__ emb_next =
        (STEP == 0) ? g_e0 : (STEP == 1) ? g_e1 : (STEP == 2) ? g_e2 : g_e3;
    const float* __restrict__ num_cur =
        (STEP == 1) ? g_n0 : (STEP == 2) ? g_n1 : g_n2;
    float* __restrict__ num_next =
        (STEP == 0) ? g_n0 : (STEP == 1) ? g_n1 : (STEP == 2) ? g_n2 : g_n3;

    int s = g_rowptr[r], e = g_rowptr[r + 1];
    float acc0 = 0.f, acc1 = 0.f, acc2 = 0.f, acc3 = 0.f;
    float accn_l = 0.f, acco_l = 0.f;

    for (int base = s; base < e; base += 32) {
        int j = base + lane;
        bool valid = j < e;
        int4 q = valid ? __ldg(&g_cve[j]) : make_int4(0, 0, 0, 0);
        int   c = q.x;
        float v = __int_as_float(q.y);
        bool nz = valid && (v != 0.f);

        if (STEP > 0) { if (nz) accn_l += v * __ldg(&num_cur[c]); }
        if (STEP < 3) {
            acco_l += v;                         // order for next step
            if (nz) {
                float m = floorf(u01(rbits32(k0, k1, (uint32_t)q.z)) + keep_prob);
                ((float*)&g_cve[j])[1] = v * m;  // store next step's val word
            }
        }

        // compact nonzero (c,v) into low lanes
        unsigned blt = __ballot_sync(0xffffffffu, nz);
        int total = __popc(blt);
        int src = __fns(blt, 0, lane + 1) & 31;
        int   cC = __shfl_sync(0xffffffffu, c, src);
        float vC = __shfl_sync(0xffffffffu, v, src);

        int t = 0;
        for (; t + 4 <= total; t += 4) {
            int   c0 = __shfl_sync(0xffffffffu, cC, t);
            int   c1 = __shfl_sync(0xffffffffu, cC, t + 1);
            int   c2 = __shfl_sync(0xffffffffu, cC, t + 2);
            int   c3 = __shfl_sync(0xffffffffu, cC, t + 3);
            float v0 = __shfl_sync(0xffffffffu, vC, t);
            float v1 = __shfl_sync(0xffffffffu, vC, t + 1);
            float v2 = __shfl_sync(0xffffffffu, vC, t + 2);
            float v3 = __shfl_sync(0xffffffffu, vC, t + 3);
            float f0 = __ldg(&emb_cur[c0 * DD + lane]);
            float f1 = __ldg(&emb_cur[c1 * DD + lane]);
            float f2 = __ldg(&emb_cur[c2 * DD + lane]);
            float f3 = __ldg(&emb_cur[c3 * DD + lane]);
            acc0 += v0 * f0; acc1 += v1 * f1; acc2 += v2 * f2; acc3 += v3 * f3;
        }
        for (; t < total; t++) {
            int   cc = __shfl_sync(0xffffffffu, cC, t);
            float vv = __shfl_sync(0xffffffffu, vC, t);
            acc0 += vv * __ldg(&emb_cur[cc * DD + lane]);
        }
    }
    // NOTE: grouping (acc0+acc1)+(acc2+acc3) is a fixed deterministic order.
    float acc = (acc0 + acc1) + (acc2 + acc3);
#pragma unroll
    for (int o = 16; o; o >>= 1) {
        if (STEP < 3) acco_l += __shfl_xor_sync(0xffffffffu, acco_l, o);
        if (STEP > 0) accn_l += __shfl_xor_sync(0xffffffffu, accn_l, o);
    }

    float ec = emb_cur[r * DD + lane];
    if (STEP == 0) {
        emb_next[r * DD + lane] = acc - ec;
        if (lane == 0) { num_next[r] = acco_l; g_order[r] = acco_l; }
    } else {
        float od = g_order[r];
        emb_next[r * DD + lane] = acc - ec - od * ec;
        if (lane == 0) {
            num_next[r] = accn_l - num_cur[r] - od;
            if (STEP < 3) g_order[r] = acco_l;
        }
    }
}

// ---------------- scoring (sum + normalize + dot + Gumbel) with fused histogram ----------------
__global__ void score_kernel(const float* __restrict__ embeds, float* __restrict__ out,
                             int n_score_out) {
    int gid = blockIdx.x * blockDim.x + threadIdx.x;
    int i = gid >> 5;
    int lane = threadIdx.x & 31;
    if (i >= NN) return;

    int idx = i * DD + lane;
    float esum = g_e0[idx] + g_e1[idx] + g_e2[idx] + g_e3[idx];
    float ns = g_n0[i] + g_n1[i] + g_n2[i] + g_n3[i] + 1e-8f;
    float sub = esum / ns;
    float em = embeds[idx];
    float ss = sub * sub, ee = em * em;
#pragma unroll
    for (int o = 16; o; o >>= 1) {
        ss += __shfl_xor_sync(0xffffffffu, ss, o);
        ee += __shfl_xor_sync(0xffffffffu, ee, o);
    }
    float a = sub / fmaxf(sqrtf(ss), 1e-12f);
    float b = em / fmaxf(sqrtf(ee), 1e-12f);
    float d = a * b;
#pragma unroll
    for (int o = 16; o; o >>= 1) d += __shfl_xor_sync(0xffffffffu, d, o);

    if (lane == 0) {
        float u = u01(rbits32(0u, 7u, (uint32_t)i));   // key(7)
        float sc = d + (-logf(-logf(u)));
        g_scores[i] = sc;
        if (i < n_score_out) out[i] = sc;
        atomicAdd(&g_hist[score_key(sc) >> (32 - HBITS)], 1);
    }
}

// ---------------- top-k: threshold + compact + bitonic ----------------
__global__ void thresh_kernel() {   // 1 block, 1024 threads
    __shared__ int part[1024];
    const int T = 1024, CH = HSIZE / 1024;   // 128
    int t = threadIdx.x;
    int s = t * CH;
    int sum = 0;
    for (int i = 0; i < CH; i++) sum += g_hist[s + i];
    part[t] = sum;
    __syncthreads();
    if (t == 0) {
        int cum = 0, d = 0;
        for (int tt = T - 1; tt >= 0; tt--) {
            if (cum + part[tt] >= KTOP) {
                for (int b = tt * CH + CH - 1; b >= tt * CH; b--) {
                    int h = g_hist[b];
                    if (cum + h >= KTOP) { d = b; break; }
                    cum += h;
                }
                break;
            }
            cum += part[tt];
        }
        g_sel_digit = d;
    }
}

__global__ void compact_kernel() {
    int i = blockIdx.x * blockDim.x + threadIdx.x;
    if (i >= NN) return;
    uint32_t k = score_key(g_scores[i]);
    if ((int)(k >> (32 - HBITS)) >= g_sel_digit) {
        int p = atomicAdd(&g_cand_cnt, 1);
        if (p < CAP) { g_cand_key[p] = k; g_cand_idx[p] = i; }
    }
}

__global__ void final_kernel(float* __restrict__ out, int out_size) {  // 1 block, 1024 thr
    __shared__ unsigned long long sm[CAP];
    int n = g_cand_cnt; if (n > CAP) n = CAP;
    int m = KTOP; while (m < n) m <<= 1;      // power-of-2 sort size (usually 2048)
    for (int i = threadIdx.x; i < m; i += blockDim.x) {
        sm[i] = (i < n)
            ? ((((unsigned long long)g_cand_key[i]) << 32) | (uint32_t)(~(uint32_t)g_cand_idx[i]))
            : 0ull;
    }
    __syncthreads();
    for (int size = 2; size <= m; size <<= 1) {
        for (int stride = size >> 1; stride > 0; stride >>= 1) {
            for (int i = threadIdx.x; i < m / 2; i += blockDim.x) {
                int lo = 2 * i - (i & (stride - 1));
                int hi = lo + stride;
                bool desc = ((lo & size) == 0);
                unsigned long long a = sm[lo], b = sm[hi];
                bool sw = desc ? (a < b) : (a > b);
                if (sw) { sm[lo] = b; sm[hi] = a; }
            }
            __syncthreads();
        }
    }
    for (int j = threadIdx.x; j < KTOP; j += blockDim.x) {
        uint32_t idx = ~(uint32_t)(sm[j] & 0xffffffffull);
        if (out_size >= NN + KTOP) out[NN + j] = (float)idx;
        else if (out_size == KTOP) ((int*)out)[j] = (int)idx;
    }
}

// ---------------- launch ----------------
extern "C" void kernel_launch(void* const* d_in, const int* in_sizes, int n_in,
                              void* d_out, int out_size) {
    const int* rows = (const int*)d_in[0];       // edge_index[0]
    const int* cols = rows + EE;                 // edge_index[1]
    const float* adj = (const float*)d_in[1];
    const float* embeds = (const float*)d_in[2];
    float* out = (float*)d_out;
    (void)in_sizes; (void)n_in;

    // fold_in(key(42), i): threefry((0,42),(0,i)) -> derived key
    uint32_t fk[3][2];
    for (uint32_t i = 0; i < 3; i++) tf2x32(0u, 42u, 0u, i, fk[i][0], fk[i][1]);

    const int tb = 256;
    zero_kernel<<<(HSIZE + tb - 1) / tb, tb>>>();
    rowcnt_kernel<<<(EE + tb - 1) / tb, tb>>>(rows);
    scan1_kernel<<<SCAN_B, 1024>>>();
    scan2_kernel<<<1, 128>>>();
    scan3_kernel<<<SCAN_B, 1024>>>();
    scatter_kernel<<<(EE + tb - 1) / tb, tb>>>(rows);
    warpsort_pack_kernel<<<(NN * 32 + tb - 1) / tb, tb>>>(cols, adj);

    step_kernel<0><<<(NN * 32 + tb - 1) / tb, tb>>>(embeds, fk[0][0], fk[0][1], 0.5f);
    step_kernel<1><<<(NN * 32 + tb - 1) / tb, tb>>>(embeds, fk[1][0], fk[1][1], 0.25f);
    step_kernel<2><<<(NN * 32 + tb - 1) / tb, tb>>>(embeds, fk[2][0], fk[2][1], 0.125f);
    step_kernel<3><<<(NN * 32 + tb - 1) / tb, tb>>>(embeds, 0u, 0u, 0.f);

    int n_score_out = (out_size == KTOP) ? 0 : ((out_size < NN) ? out_size : NN);
    score_kernel<<<(NN * 32 + tb - 1) / tb, tb>>>(embeds, out, n_score_out);

    thresh_kernel<<<1, 1024>>>();
    compact_kernel<<<(NN + tb - 1) / tb, tb>>>();
    final_kernel<<<1, 1024>>>(out, out_size);
}

// round 11
// speedup vs baseline: 1.1693x; 1.0186x over previous
#include <cuda_runtime.h>
#include <stdint.h>

#define NN 100000
#define EE 1600000
#define DD 32
#define KTOP 1024
#define HBITS 17
#define HSIZE (1 << HBITS)
#define CAP 4096
#define SCAN_B 98   // ceil(NN / 1024)

// ---------------- scratch (device globals; no allocation allowed) ----------------
__device__ int    g_rowcnt[NN];
__device__ int    g_rowptr[NN + 1];
__device__ int    g_cursor[NN];
__device__ int    g_perm[EE];
__device__ int4   g_cve[EE];                      // (col, val bits, eid, pad); compacted in-row per step
__device__ int    g_deg[NN];                      // live degree after latest mask
__device__ float  g_e0[NN * DD], g_e1[NN * DD], g_e2[NN * DD];
__device__ float  g_n0[NN], g_n1[NN], g_n2[NN];
__device__ float  g_order[NN];
__device__ float  g_scores[NN];
__device__ int    g_hist[HSIZE];
__device__ int    g_blockTot[SCAN_B], g_blockOff[SCAN_B];
__device__ int    g_sel_digit;
__device__ int    g_cand_cnt;
__device__ unsigned int g_cand_key[CAP];
__device__ int    g_cand_idx[CAP];

// ---------------- threefry2x32 (JAX-compatible, partitionable mode) ----------------
__host__ __device__ __forceinline__ void tf2x32(uint32_t k0, uint32_t k1,
                                                uint32_t x0, uint32_t x1,
                                                uint32_t &o0, uint32_t &o1) {
    uint32_t ks2 = k0 ^ k1 ^ 0x1BD11BDAu;
    x0 += k0; x1 += k1;
#define TFR(r) do { x0 += x1; x1 = (x1 << (r)) | (x1 >> (32 - (r))); x1 ^= x0; } while (0)
    TFR(13); TFR(15); TFR(26); TFR(6);
    x0 += k1;  x1 += ks2 + 1u;
    TFR(17); TFR(29); TFR(16); TFR(24);
    x0 += ks2; x1 += k0 + 2u;
    TFR(13); TFR(15); TFR(26); TFR(6);
    x0 += k0;  x1 += k1 + 3u;
    TFR(17); TFR(29); TFR(16); TFR(24);
    x0 += k1;  x1 += ks2 + 4u;
    TFR(13); TFR(15); TFR(26); TFR(6);
    x0 += ks2; x1 += k0 + 5u;
#undef TFR
    o0 = x0; o1 = x1;
}

__device__ __forceinline__ uint32_t rbits32(uint32_t k0, uint32_t k1, uint32_t i) {
    uint32_t a, b;
    tf2x32(k0, k1, 0u, i, a, b);
    return a ^ b;
}

__device__ __forceinline__ float u01(uint32_t bits) {
    return __uint_as_float((bits >> 9) | 0x3f800000u) - 1.0f;
}

__device__ __forceinline__ uint32_t score_key(float f) {
    uint32_t b = __float_as_uint(f);
    return (b & 0x80000000u) ? ~b : (b | 0x80000000u);
}

// ---------------- init ----------------
__global__ void zero_kernel() {
    int i = blockIdx.x * blockDim.x + threadIdx.x;
    if (i < HSIZE) g_hist[i] = 0;
    if (i < NN) g_rowcnt[i] = 0;
    if (i == 0) g_cand_cnt = 0;
}

__global__ void rowcnt_kernel(const int* __restrict__ rows) {
    int e = blockIdx.x * blockDim.x + threadIdx.x;
    if (e >= EE) return;
    atomicAdd(&g_rowcnt[rows[e]], 1);
}

// ---------------- 3-phase exclusive scan of rowcnt -> rowptr ----------------
__global__ void scan1_kernel() {           // SCAN_B blocks x 1024
    __shared__ int sm[1024];
    int t = threadIdx.x, b = blockIdx.x, i = b * 1024 + t;
    int x = (i < NN) ? g_rowcnt[i] : 0;
    sm[t] = x;
    __syncthreads();
    for (int off = 1; off < 1024; off <<= 1) {
        int y = (t >= off) ? sm[t - off] : 0;
        __syncthreads();
        sm[t] += y;
        __syncthreads();
    }
    if (i < NN) g_rowptr[i] = sm[t] - x;   // local exclusive
    if (t == 1023) g_blockTot[b] = sm[t];
}

__global__ void scan2_kernel() {           // 1 block x 128
    __shared__ int sm[128];
    int t = threadIdx.x;
    int x = (t < SCAN_B) ? g_blockTot[t] : 0;
    sm[t] = x;
    __syncthreads();
    for (int off = 1; off < 128; off <<= 1) {
        int y = (t >= off) ? sm[t - off] : 0;
        __syncthreads();
        sm[t] += y;
        __syncthreads();
    }
    if (t < SCAN_B) g_blockOff[t] = sm[t] - x;   // exclusive
    if (t == SCAN_B - 1) g_rowptr[NN] = sm[t];
}

__global__ void scan3_kernel() {           // add offsets, init cursor
    int t = threadIdx.x, b = blockIdx.x, i = b * 1024 + t;
    if (i < NN) {
        int v = g_rowptr[i] + g_blockOff[b];
        g_rowptr[i] = v;
        g_cursor[i] = v;
    }
}

__global__ void scatter_kernel(const int* __restrict__ rows) {
    int e = blockIdx.x * blockDim.x + threadIdx.x;
    if (e >= EE) return;
    int pos = atomicAdd(&g_cursor[rows[e]], 1);
    g_perm[pos] = e;
}

// Warp-per-row: sort edge ids (deterministic order), then gather (col, adj)
// and write the packed int4 CSR edge array directly from registers.
__global__ void warpsort_pack_kernel(const int* __restrict__ cols,
                                     const float* __restrict__ adj) {
    int gid = blockIdx.x * blockDim.x + threadIdx.x;
    int r = gid >> 5;
    int lane = threadIdx.x & 31;
    if (r >= NN) return;
    int s = g_rowptr[r], e = g_rowptr[r + 1];
    int deg = e - s;
    if (deg == 0) return;
    if (deg <= 32) {
        int v = (lane < deg) ? g_perm[s + lane] : 0x7fffffff;
#pragma unroll
        for (int k = 2; k <= 32; k <<= 1) {
#pragma unroll
            for (int j = k >> 1; j > 0; j >>= 1) {
                int o = __shfl_xor_sync(0xffffffffu, v, j);
                bool dir = ((lane & k) == 0);
                bool lower = ((lane & j) == 0);
                int mn = min(v, o), mx = max(v, o);
                v = (dir == lower) ? mn : mx;
            }
        }
        if (lane < deg) {
            int   c = __ldg(&cols[v]);
            float a = __ldg(&adj[v]);
            g_cve[s + lane] = make_int4(c, __float_as_int(a), v, 0);
        }
    } else {
        if (lane == 0) {
            for (int i = s + 1; i < e; i++) {
                int v = g_perm[i];
                int j = i - 1;
                while (j >= s && g_perm[j] > v) { g_perm[j + 1] = g_perm[j]; j--; }
                g_perm[j + 1] = v;
            }
        }
        __syncwarp();
        for (int j = s + lane; j < e; j += 32) {
            int eid = g_perm[j];
            g_cve[j] = make_int4(__ldg(&cols[eid]), __float_as_int(__ldg(&adj[eid])), eid, 0);
        }
    }
}

// ---------------- fused propagation step (STEP = 0,1,2) ----------------
// Warp per row, lane = dim. Iterates only the live edge list (g_deg), gathers
// via quad-unrolled broadcast (MLP=4), applies this step's dropout mask
// (threefry) and compacts survivors to the front of the row's segment
// (stable ballot/prefix order -> deterministic), writing the new degree.
template <int STEP>
__global__ void step_kernel(const float* __restrict__ embeds,
                            uint32_t k0, uint32_t k1, float keep_prob) {
    int gid = blockIdx.x * blockDim.x + threadIdx.x;
    int r = gid >> 5;
    int lane = threadIdx.x & 31;
    if (r >= NN) return;

    const float* __restrict__ emb_cur =
        (STEP == 0) ? embeds : (STEP == 1) ? g_e0 : g_e1;
    float* __restrict__ emb_next =
        (STEP == 0) ? g_e0 : (STEP == 1) ? g_e1 : g_e2;
    const float* __restrict__ num_cur =
        (STEP == 1) ? g_n0 : g_n1;                  // unused for STEP==0
    float* __restrict__ num_next =
        (STEP == 0) ? g_n0 : (STEP == 1) ? g_n1 : g_n2;

    int s = g_rowptr[r];
    int deg = (STEP == 0) ? (g_rowptr[r + 1] - s) : g_deg[r];
    int e = s + deg;
    float acc0 = 0.f, acc1 = 0.f, acc2 = 0.f, acc3 = 0.f;
    float accn_l = 0.f, acco_l = 0.f;
    int cnt = 0;   // survivors written so far (compaction cursor)

    for (int base = s; base < e; base += 32) {
        int j = base + lane;
        bool valid = j < e;
        int4 q = valid ? __ldg(&g_cve[j]) : make_int4(0, 0, 0, 0);
        int   c = q.x;
        float v = __int_as_float(q.y);

        if (STEP > 0) { if (valid) accn_l += v * __ldg(&num_cur[c]); }
        acco_l += v;

        // dropout mask for this step; survivors compacted to front of segment.
        bool keep = false;
        if (valid && v != 0.f) {
            float m = floorf(u01(rbits32(k0, k1, (uint32_t)q.z)) + keep_prob);
            keep = (m != 0.f);
        }
        unsigned kb = __ballot_sync(0xffffffffu, keep);   // also a sync point:
        int pref = __popc(kb & ((1u << lane) - 1));       // all chunk loads consumed
        if (keep) g_cve[s + cnt + pref] = q;              // v unchanged (binary mask)
        cnt += __popc(kb);

        // gather over valid lanes (zero-val entries contribute exact 0)
        int tot = min(32, e - base);
        int t = 0;
        for (; t + 4 <= tot; t += 4) {
            int   c0 = __shfl_sync(0xffffffffu, c, t);
            int   c1 = __shfl_sync(0xffffffffu, c, t + 1);
            int   c2 = __shfl_sync(0xffffffffu, c, t + 2);
            int   c3 = __shfl_sync(0xffffffffu, c, t + 3);
            float v0 = __shfl_sync(0xffffffffu, v, t);
            float v1 = __shfl_sync(0xffffffffu, v, t + 1);
            float v2 = __shfl_sync(0xffffffffu, v, t + 2);
            float v3 = __shfl_sync(0xffffffffu, v, t + 3);
            float f0 = __ldg(&emb_cur[c0 * DD + lane]);
            float f1 = __ldg(&emb_cur[c1 * DD + lane]);
            float f2 = __ldg(&emb_cur[c2 * DD + lane]);
            float f3 = __ldg(&emb_cur[c3 * DD + lane]);
            acc0 += v0 * f0; acc1 += v1 * f1; acc2 += v2 * f2; acc3 += v3 * f3;
        }
        for (; t < tot; t++) {
            int   cc = __shfl_sync(0xffffffffu, c, t);
            float vv = __shfl_sync(0xffffffffu, v, t);
            acc0 += vv * __ldg(&emb_cur[cc * DD + lane]);
        }
    }
    float acc = (acc0 + acc1) + (acc2 + acc3);   // fixed deterministic grouping
#pragma unroll
    for (int o = 16; o; o >>= 1) {
        acco_l += __shfl_xor_sync(0xffffffffu, acco_l, o);
        if (STEP > 0) accn_l += __shfl_xor_sync(0xffffffffu, accn_l, o);
    }

    float ec = emb_cur[r * DD + lane];
    if (STEP == 0) {
        emb_next[r * DD + lane] = acc - ec;
        if (lane == 0) { num_next[r] = acco_l; g_order[r] = acco_l; g_deg[r] = cnt; }
    } else {
        float od = g_order[r];
        emb_next[r * DD + lane] = acc - ec - od * ec;
        if (lane == 0) {
            num_next[r] = accn_l - num_cur[r] - od;
            g_order[r] = acco_l;
            g_deg[r] = cnt;
        }
    }
}

// ---------------- final step (mask-depth 3) fused with scoring ----------------
// Computes en3/n3 in registers from the 3rd-compacted edge list (~1.6% of E),
// then sums emb/num, normalizes, dots with normalized embeds, adds Gumbel,
// stores score, and feeds the top-k histogram.
__global__ void score_kernel(const float* __restrict__ embeds, float* __restrict__ out,
                             int n_score_out) {
    int gid = blockIdx.x * blockDim.x + threadIdx.x;
    int r = gid >> 5;
    int lane = threadIdx.x & 31;
    if (r >= NN) return;

    int s = g_rowptr[r];
    int e = s + g_deg[r];
    float acc0 = 0.f, acc1 = 0.f, acc2 = 0.f, acc3 = 0.f, accn_l = 0.f;

    for (int base = s; base < e; base += 32) {
        int j = base + lane;
        bool valid = j < e;
        int4 q = valid ? __ldg(&g_cve[j]) : make_int4(0, 0, 0, 0);
        int   c = q.x;
        float v = __int_as_float(q.y);
        if (valid) accn_l += v * __ldg(&g_n2[c]);
        int tot = min(32, e - base);
        int t = 0;
        for (; t + 4 <= tot; t += 4) {
            int   c0 = __shfl_sync(0xffffffffu, c, t);
            int   c1 = __shfl_sync(0xffffffffu, c, t + 1);
            int   c2 = __shfl_sync(0xffffffffu, c, t + 2);
            int   c3 = __shfl_sync(0xffffffffu, c, t + 3);
            float v0 = __shfl_sync(0xffffffffu, v, t);
            float v1 = __shfl_sync(0xffffffffu, v, t + 1);
            float v2 = __shfl_sync(0xffffffffu, v, t + 2);
            float v3 = __shfl_sync(0xffffffffu, v, t + 3);
            acc0 += v0 * __ldg(&g_e2[c0 * DD + lane]);
            acc1 += v1 * __ldg(&g_e2[c1 * DD + lane]);
            acc2 += v2 * __ldg(&g_e2[c2 * DD + lane]);
            acc3 += v3 * __ldg(&g_e2[c3 * DD + lane]);
        }
        for (; t < tot; t++) {
            int   cc = __shfl_sync(0xffffffffu, c, t);
            float vv = __shfl_sync(0xffffffffu, v, t);
            acc0 += vv * __ldg(&g_e2[cc * DD + lane]);
        }
    }
    float acc = (acc0 + acc1) + (acc2 + acc3);
#pragma unroll
    for (int o = 16; o; o >>= 1)
        accn_l += __shfl_xor_sync(0xffffffffu, accn_l, o);   // all lanes get n-spmm

    int idx = r * DD + lane;
    float ec = g_e2[idx];
    float od = g_order[r];
    float en3 = acc - ec - od * ec;
    float n2r = g_n2[r];
    float n3 = accn_l - n2r - od;

    float esum = g_e0[idx] + g_e1[idx] + ec + en3;
    float ns = g_n0[r] + g_n1[r] + n2r + n3 + 1e-8f;
    float sub = esum / ns;
    float em = embeds[idx];
    float ss = sub * sub, ee2 = em * em;
#pragma unroll
    for (int o = 16; o; o >>= 1) {
        ss += __shfl_xor_sync(0xffffffffu, ss, o);
        ee2 += __shfl_xor_sync(0xffffffffu, ee2, o);
    }
    float a = sub / fmaxf(sqrtf(ss), 1e-12f);
    float b = em / fmaxf(sqrtf(ee2), 1e-12f);
    float d = a * b;
#pragma unroll
    for (int o = 16; o; o >>= 1) d += __shfl_xor_sync(0xffffffffu, d, o);

    if (lane == 0) {
        float u = u01(rbits32(0u, 7u, (uint32_t)r));   // key(7)
        float sc = d + (-logf(-logf(u)));
        g_scores[r] = sc;
        if (r < n_score_out) out[r] = sc;
        atomicAdd(&g_hist[score_key(sc) >> (32 - HBITS)], 1);
    }
}

// ---------------- top-k: threshold + compact + bitonic ----------------
__global__ void thresh_kernel() {   // 1 block, 1024 threads
    __shared__ int part[1024];
    const int T = 1024, CH = HSIZE / 1024;   // 128
    int t = threadIdx.x;
    int s = t * CH;
    int sum = 0;
    for (int i = 0; i < CH; i++) sum += g_hist[s + i];
    part[t] = sum;
    __syncthreads();
    if (t == 0) {
        int cum = 0, d = 0;
        for (int tt = T - 1; tt >= 0; tt--) {
            if (cum + part[tt] >= KTOP) {
                for (int b = tt * CH + CH - 1; b >= tt * CH; b--) {
                    int h = g_hist[b];
                    if (cum + h >= KTOP) { d = b; break; }
                    cum += h;
                }
                break;
            }
            cum += part[tt];
        }
        g_sel_digit = d;
    }
}

__global__ void compact_kernel() {
    int i = blockIdx.x * blockDim.x + threadIdx.x;
    if (i >= NN) return;
    uint32_t k = score_key(g_scores[i]);
    if ((int)(k >> (32 - HBITS)) >= g_sel_digit) {
        int p = atomicAdd(&g_cand_cnt, 1);
        if (p < CAP) { g_cand_key[p] = k; g_cand_idx[p] = i; }
    }
}

__global__ void final_kernel(float* __restrict__ out, int out_size) {  // 1 block, 1024 thr
    __shared__ unsigned long long sm[CAP];
    int n = g_cand_cnt; if (n > CAP) n = CAP;
    int m = KTOP; while (m < n) m <<= 1;      // power-of-2 sort size (usually 2048)
    for (int i = threadIdx.x; i < m; i += blockDim.x) {
        sm[i] = (i < n)
            ? ((((unsigned long long)g_cand_key[i]) << 32) | (uint32_t)(~(uint32_t)g_cand_idx[i]))
            : 0ull;
    }
    __syncthreads();
    for (int size = 2; size <= m; size <<= 1) {
        for (int stride = size >> 1; stride > 0; stride >>= 1) {
            for (int i = threadIdx.x; i < m / 2; i += blockDim.x) {
                int lo = 2 * i - (i & (stride - 1));
                int hi = lo + stride;
                bool desc = ((lo & size) == 0);
                unsigned long long a = sm[lo], b = sm[hi];
                bool sw = desc ? (a < b) : (a > b);
                if (sw) { sm[lo] = b; sm[hi] = a; }
            }
            __syncthreads();
        }
    }
    for (int j = threadIdx.x; j < KTOP; j += blockDim.x) {
        uint32_t idx = ~(uint32_t)(sm[j] & 0xffffffffull);
        if (out_size >= NN + KTOP) out[NN + j] = (float)idx;
        else if (out_size == KTOP) ((int*)out)[j] = (int)idx;
    }
}

// ---------------- launch ----------------
extern "C" void kernel_launch(void* const* d_in, const int* in_sizes, int n_in,
                              void* d_out, int out_size) {
    const int* rows = (const int*)d_in[0];       // edge_index[0]
    const int* cols = rows + EE;                 // edge_index[1]
    const float* adj = (const float*)d_in[1];
    const float* embeds = (const float*)d_in[2];
    float* out = (float*)d_out;
    (void)in_sizes; (void)n_in;

    // fold_in(key(42), i): threefry((0,42),(0,i)) -> derived key
    uint32_t fk[3][2];
    for (uint32_t i = 0; i < 3; i++) tf2x32(0u, 42u, 0u, i, fk[i][0], fk[i][1]);

    const int tb = 256;
    zero_kernel<<<(HSIZE + tb - 1) / tb, tb>>>();
    rowcnt_kernel<<<(EE + tb - 1) / tb, tb>>>(rows);
    scan1_kernel<<<SCAN_B, 1024>>>();
    scan2_kernel<<<1, 128>>>();
    scan3_kernel<<<SCAN_B, 1024>>>();
    scatter_kernel<<<(EE + tb - 1) / tb, tb>>>(rows);
    warpsort_pack_kernel<<<(NN * 32 + tb - 1) / tb, tb>>>(cols, adj);

    step_kernel<0><<<(NN * 32 + tb - 1) / tb, tb>>>(embeds, fk[0][0], fk[0][1], 0.5f);
    step_kernel<1><<<(NN * 32 + tb - 1) / tb, tb>>>(embeds, fk[1][0], fk[1][1], 0.25f);
    step_kernel<2><<<(NN * 32 + tb - 1) / tb, tb>>>(embeds, fk[2][0], fk[2][1], 0.125f);

    int n_score_out = (out_size == KTOP) ? 0 : ((out_size < NN) ? out_size : NN);
    score_kernel<<<(NN * 32 + tb - 1) / tb, tb>>>(embeds, out, n_score_out);

    thresh_kernel<<<1, 1024>>>();
    compact_kernel<<<(NN + tb - 1) / tb, tb>>>();
    final_kernel<<<1, 1024>>>(out, out_size);
}

// round 14
// speedup vs baseline: 1.2503x; 1.0692x over previous
#include <cuda_runtime.h>
#include <stdint.h>

#define NN 100000
#define EE 1600000
#define DD 32
#define KTOP 1024
#define HBITS 17
#define HSIZE (1 << HBITS)
#define CAP 4096
#define TPB 256

// ---------------- scratch (device globals; no allocation allowed) ----------------
__device__ int    g_rowcnt[NN];
__device__ int    g_rowptr[NN + 1];
__device__ int    g_cursor[NN];
__device__ int    g_perm[EE];
__device__ int4   g_cve[EE];             // (col, val bits, eid, pad); compacted in-row per step
__device__ int    g_deg[NN];
__device__ float  g_e0[NN * DD], g_e1[NN * DD], g_e2[NN * DD];
__device__ float  g_n0[NN], g_n1[NN], g_n2[NN];
__device__ float  g_order[NN];
__device__ float  g_scores[NN];
__device__ int    g_hist[HSIZE];
__device__ int    g_blockTot[2048], g_blockOff[2048];
__device__ int    g_chunkSum[1024];
__device__ int    g_sel_digit;
__device__ int    g_cand_cnt;
__device__ unsigned int g_cand_key[CAP];
__device__ int    g_cand_idx[CAP];
// software grid barrier state (zero-init; count returns to 0 after each barrier,
// generation increases monotonically across barriers and launches)
__device__ int    g_bar_count;
__device__ volatile unsigned g_bar_gen;

// ---------------- threefry2x32 (JAX-compatible, partitionable mode) ----------------
__host__ __device__ __forceinline__ void tf2x32(uint32_t k0, uint32_t k1,
                                                uint32_t x0, uint32_t x1,
                                                uint32_t &o0, uint32_t &o1) {
    uint32_t ks2 = k0 ^ k1 ^ 0x1BD11BDAu;
    x0 += k0; x1 += k1;
#define TFR(r) do { x0 += x1; x1 = (x1 << (r)) | (x1 >> (32 - (r))); x1 ^= x0; } while (0)
    TFR(13); TFR(15); TFR(26); TFR(6);
    x0 += k1;  x1 += ks2 + 1u;
    TFR(17); TFR(29); TFR(16); TFR(24);
    x0 += ks2; x1 += k0 + 2u;
    TFR(13); TFR(15); TFR(26); TFR(6);
    x0 += k0;  x1 += k1 + 3u;
    TFR(17); TFR(29); TFR(16); TFR(24);
    x0 += k1;  x1 += ks2 + 4u;
    TFR(13); TFR(15); TFR(26); TFR(6);
    x0 += ks2; x1 += k0 + 5u;
#undef TFR
    o0 = x0; o1 = x1;
}

__device__ __forceinline__ uint32_t rbits32(uint32_t k0, uint32_t k1, uint32_t i) {
    uint32_t a, b;
    tf2x32(k0, k1, 0u, i, a, b);
    return a ^ b;
}

__device__ __forceinline__ float u01(uint32_t bits) {
    return __uint_as_float((bits >> 9) | 0x3f800000u) - 1.0f;
}

__device__ __forceinline__ uint32_t score_key(float f) {
    uint32_t b = __float_as_uint(f);
    return (b & 0x80000000u) ? ~b : (b | 0x80000000u);
}

// ---------------- software grid barrier (all blocks co-resident by construction) ----
__device__ __forceinline__ void gbar() {
    __syncthreads();
    if (threadIdx.x == 0) {
        unsigned gen = g_bar_gen;
        __threadfence();
        if (atomicAdd(&g_bar_count, 1) == (int)gridDim.x - 1) {
            g_bar_count = 0;
            __threadfence();
            g_bar_gen = gen + 1;
        } else {
            while (g_bar_gen == gen) __nanosleep(64);
            __threadfence();
        }
    }
    __syncthreads();
}

// ---------------- propagation step (STEP = 0,1,2), warp-per-row grid-stride -------
template <int STEP>
__device__ void do_step(int gwarp, int nwarps, int lane, const float* embeds,
                        uint32_t k0, uint32_t k1, float keep_prob) {
    const float* emb_cur = (STEP == 0) ? embeds : (STEP == 1) ? g_e0 : g_e1;
    float*       emb_next = (STEP == 0) ? g_e0 : (STEP == 1) ? g_e1 : g_e2;
    const float* num_cur = (STEP == 1) ? g_n0 : g_n1;   // unused for STEP==0
    float*       num_next = (STEP == 0) ? g_n0 : (STEP == 1) ? g_n1 : g_n2;

    for (int r = gwarp; r < NN; r += nwarps) {
        int s = __ldcg(&g_rowptr[r]);
        int deg = (STEP == 0) ? (__ldcg(&g_rowptr[r + 1]) - s) : g_deg[r];
        int e = s + deg;
        float acc0 = 0.f, acc1 = 0.f, acc2 = 0.f, acc3 = 0.f;
        float accn_l = 0.f, acco_l = 0.f;
        int cnt = 0;

        for (int base = s; base < e; base += 32) {
            int j = base + lane;
            bool valid = j < e;
            int4 q = valid ? g_cve[j] : make_int4(0, 0, 0, 0);
            int   c = q.x;
            float v = __int_as_float(q.y);

            if (STEP > 0) { if (valid) accn_l += v * num_cur[c]; }
            acco_l += v;

            bool keep = false;
            if (valid && v != 0.f) {
                float m = floorf(u01(rbits32(k0, k1, (uint32_t)q.z)) + keep_prob);
                keep = (m != 0.f);
            }
            unsigned kb = __ballot_sync(0xffffffffu, keep);   // sync: all loads consumed
            int pref = __popc(kb & ((1u << lane) - 1));
            if (keep) g_cve[s + cnt + pref] = q;
            cnt += __popc(kb);

            int tot = min(32, e - base);
            int t = 0;
            for (; t + 4 <= tot; t += 4) {
                int   c0 = __shfl_sync(0xffffffffu, c, t);
                int   c1 = __shfl_sync(0xffffffffu, c, t + 1);
                int   c2 = __shfl_sync(0xffffffffu, c, t + 2);
                int   c3 = __shfl_sync(0xffffffffu, c, t + 3);
                float v0 = __shfl_sync(0xffffffffu, v, t);
                float v1 = __shfl_sync(0xffffffffu, v, t + 1);
                float v2 = __shfl_sync(0xffffffffu, v, t + 2);
                float v3 = __shfl_sync(0xffffffffu, v, t + 3);
                float f0 = (STEP == 0) ? __ldg(&emb_cur[c0 * DD + lane]) : emb_cur[c0 * DD + lane];
                float f1 = (STEP == 0) ? __ldg(&emb_cur[c1 * DD + lane]) : emb_cur[c1 * DD + lane];
                float f2 = (STEP == 0) ? __ldg(&emb_cur[c2 * DD + lane]) : emb_cur[c2 * DD + lane];
                float f3 = (STEP == 0) ? __ldg(&emb_cur[c3 * DD + lane]) : emb_cur[c3 * DD + lane];
                acc0 += v0 * f0; acc1 += v1 * f1; acc2 += v2 * f2; acc3 += v3 * f3;
            }
            for (; t < tot; t++) {
                int   cc = __shfl_sync(0xffffffffu, c, t);
                float vv = __shfl_sync(0xffffffffu, v, t);
                float ff = (STEP == 0) ? __ldg(&emb_cur[cc * DD + lane]) : emb_cur[cc * DD + lane];
                acc0 += vv * ff;
            }
        }
        float acc = (acc0 + acc1) + (acc2 + acc3);   // fixed deterministic grouping
#pragma unroll
        for (int o = 16; o; o >>= 1) {
            acco_l += __shfl_xor_sync(0xffffffffu, acco_l, o);
            if (STEP > 0) accn_l += __shfl_xor_sync(0xffffffffu, accn_l, o);
        }

        float ec = (STEP == 0) ? __ldg(&emb_cur[r * DD + lane]) : emb_cur[r * DD + lane];
        if (STEP == 0) {
            emb_next[r * DD + lane] = acc - ec;
            if (lane == 0) { num_next[r] = acco_l; g_order[r] = acco_l; g_deg[r] = cnt; }
        } else {
            float od = g_order[r];
            emb_next[r * DD + lane] = acc - ec - od * ec;
            if (lane == 0) {
                num_next[r] = accn_l - num_cur[r] - od;
                g_order[r] = acco_l;
                g_deg[r] = cnt;
            }
        }
    }
}

// ---------------- THE kernel: everything in one launch ----------------
__global__ void mega_kernel(const int* __restrict__ rows, const int* __restrict__ cols,
                            const float* __restrict__ adj, const float* __restrict__ embeds,
                            float* out, int out_size, int n_score_out,
                            uint32_t a0, uint32_t a1, uint32_t b0, uint32_t b1,
                            uint32_t c0, uint32_t c1) {
    __shared__ unsigned long long sm_sort[CAP];   // 32KB; reused as int scratch
    __shared__ int sm_small[16];
    int* sm_i = (int*)sm_sort;

    const int B = gridDim.x, t = threadIdx.x, bb = blockIdx.x;
    const int gtid = bb * TPB + t, nthreads = B * TPB;
    const int lane = t & 31;
    const int gwarp = gtid >> 5, nwarps = nthreads >> 5;

    // ---- A: zero counters ----
    for (int i = gtid; i < HSIZE; i += nthreads) g_hist[i] = 0;
    for (int i = gtid; i < NN; i += nthreads) g_rowcnt[i] = 0;
    if (gtid == 0) g_cand_cnt = 0;
    gbar();

    // ---- B: row counts ----
    for (int e = gtid; e < EE; e += nthreads) atomicAdd(&g_rowcnt[__ldg(&rows[e])], 1);
    gbar();

    // ---- C1: per-thread chunk sums + block scan ----
    const int CH = (NN + nthreads - 1) / nthreads;
    const int c_lo = min(gtid * CH, NN), c_hi = min(c_lo + CH, NN);
    int csum = 0;
    for (int i = c_lo; i < c_hi; i++) csum += __ldcg(&g_rowcnt[i]);
    int x = csum;
#pragma unroll
    for (int o = 1; o < 32; o <<= 1) { int y = __shfl_up_sync(0xffffffffu, x, o); if (lane >= o) x += y; }
    if (lane == 31) sm_small[t >> 5] = x;
    __syncthreads();
    if (t == 0) { int run = 0; for (int i = 0; i < 8; i++) { int v = sm_small[i]; sm_small[i] = run; run += v; } sm_small[8] = run; }
    __syncthreads();
    const int excl_in_blk = (x - csum) + sm_small[t >> 5];
    if (t == 0) g_blockTot[bb] = sm_small[8];
    gbar();

    // ---- C2: block 0 scans block totals ----
    if (bb == 0) {
        int CHB = (B + TPB - 1) / TPB;
        int lo = min(t * CHB, B), hi = min(lo + CHB, B);
        int s2 = 0;
        for (int i = lo; i < hi; i++) s2 += __ldcg(&g_blockTot[i]);
        int x2 = s2;
#pragma unroll
        for (int o = 1; o < 32; o <<= 1) { int y = __shfl_up_sync(0xffffffffu, x2, o); if (lane >= o) x2 += y; }
        if (lane == 31) sm_small[t >> 5] = x2;
        __syncthreads();
        if (t == 0) { int run = 0; for (int i = 0; i < 8; i++) { int v = sm_small[i]; sm_small[i] = run; run += v; } }
        __syncthreads();
        int run = (x2 - s2) + sm_small[t >> 5];
        for (int i = lo; i < hi; i++) { g_blockOff[i] = run; run += __ldcg(&g_blockTot[i]); }
    }
    gbar();

    // ---- C3: write rowptr + cursor ----
    {
        int run = __ldcg(&g_blockOff[bb]) + excl_in_blk;
        for (int i = c_lo; i < c_hi; i++) {
            g_rowptr[i] = run;
            g_cursor[i] = run;
            run += __ldcg(&g_rowcnt[i]);
        }
        if (gtid == 0) g_rowptr[NN] = EE;
    }
    gbar();

    // ---- D: scatter edge ids into rows ----
    for (int e = gtid; e < EE; e += nthreads) {
        int pos = atomicAdd(&g_cursor[__ldg(&rows[e])], 1);
        g_perm[pos] = e;
    }
    gbar();

    // ---- E: warp-per-row sort (deterministic order) + pack (col, adj, eid) ----
    for (int r = gwarp; r < NN; r += nwarps) {
        int s = __ldcg(&g_rowptr[r]), e = __ldcg(&g_rowptr[r + 1]);
        int deg = e - s;
        if (deg == 0) continue;
        if (deg <= 32) {
            int v = (lane < deg) ? g_perm[s + lane] : 0x7fffffff;
#pragma unroll
            for (int k = 2; k <= 32; k <<= 1) {
#pragma unroll
                for (int j = k >> 1; j > 0; j >>= 1) {
                    int o = __shfl_xor_sync(0xffffffffu, v, j);
                    bool dir = ((lane & k) == 0);
                    bool lower = ((lane & j) == 0);
                    int mn = min(v, o), mx = max(v, o);
                    v = (dir == lower) ? mn : mx;
                }
            }
            if (lane < deg) {
                int   c = __ldg(&cols[v]);
                float a = __ldg(&adj[v]);
                g_cve[s + lane] = make_int4(c, __float_as_int(a), v, 0);
            }
        } else {
            if (lane == 0) {
                for (int i = s + 1; i < e; i++) {
                    int v = g_perm[i];
                    int j = i - 1;
                    while (j >= s && g_perm[j] > v) { g_perm[j + 1] = g_perm[j]; j--; }
                    g_perm[j + 1] = v;
                }
            }
            __syncwarp();
            for (int j = s + lane; j < e; j += 32) {
                int eid = g_perm[j];
                g_cve[j] = make_int4(__ldg(&cols[eid]), __float_as_int(__ldg(&adj[eid])), eid, 0);
            }
        }
    }
    gbar();

    // ---- F/G/H: propagation steps 0..2 ----
    do_step<0>(gwarp, nwarps, lane, embeds, a0, a1, 0.5f);
    gbar();
    do_step<1>(gwarp, nwarps, lane, embeds, b0, b1, 0.25f);
    gbar();
    do_step<2>(gwarp, nwarps, lane, embeds, c0, c1, 0.125f);
    gbar();

    // ---- I: final step (depth 3) fused with scoring + histogram ----
    for (int r = gwarp; r < NN; r += nwarps) {
        int s = __ldcg(&g_rowptr[r]);
        int e = s + g_deg[r];
        float acc0 = 0.f, acc1 = 0.f, acc2 = 0.f, acc3 = 0.f, accn_l = 0.f;

        for (int base = s; base < e; base += 32) {
            int j = base + lane;
            bool valid = j < e;
            int4 q = valid ? g_cve[j] : make_int4(0, 0, 0, 0);
            int   c = q.x;
            float v = __int_as_float(q.y);
            if (valid) accn_l += v * g_n2[c];
            int tot = min(32, e - base);
            int tt = 0;
            for (; tt + 4 <= tot; tt += 4) {
                int   c0i = __shfl_sync(0xffffffffu, c, tt);
                int   c1i = __shfl_sync(0xffffffffu, c, tt + 1);
                int   c2i = __shfl_sync(0xffffffffu, c, tt + 2);
                int   c3i = __shfl_sync(0xffffffffu, c, tt + 3);
                float v0 = __shfl_sync(0xffffffffu, v, tt);
                float v1 = __shfl_sync(0xffffffffu, v, tt + 1);
                float v2 = __shfl_sync(0xffffffffu, v, tt + 2);
                float v3 = __shfl_sync(0xffffffffu, v, tt + 3);
                acc0 += v0 * g_e2[c0i * DD + lane];
                acc1 += v1 * g_e2[c1i * DD + lane];
                acc2 += v2 * g_e2[c2i * DD + lane];
                acc3 += v3 * g_e2[c3i * DD + lane];
            }
            for (; tt < tot; tt++) {
                int   cc = __shfl_sync(0xffffffffu, c, tt);
                float vv = __shfl_sync(0xffffffffu, v, tt);
                acc0 += vv * g_e2[cc * DD + lane];
            }
        }
        float acc = (acc0 + acc1) + (acc2 + acc3);
#pragma unroll
        for (int o = 16; o; o >>= 1) accn_l += __shfl_xor_sync(0xffffffffu, accn_l, o);

        int idx = r * DD + lane;
        float ec = g_e2[idx];
        float od = g_order[r];
        float en3 = acc - ec - od * ec;
        float n2r = g_n2[r];
        float n3 = accn_l - n2r - od;

        float esum = g_e0[idx] + g_e1[idx] + ec + en3;
        float ns = g_n0[r] + g_n1[r] + n2r + n3 + 1e-8f;
        float sub = esum / ns;
        float em = __ldg(&embeds[idx]);
        float ss = sub * sub, ee2 = em * em;
#pragma unroll
        for (int o = 16; o; o >>= 1) {
            ss += __shfl_xor_sync(0xffffffffu, ss, o);
            ee2 += __shfl_xor_sync(0xffffffffu, ee2, o);
        }
        float na = sub / fmaxf(sqrtf(ss), 1e-12f);
        float nb = em / fmaxf(sqrtf(ee2), 1e-12f);
        float d = na * nb;
#pragma unroll
        for (int o = 16; o; o >>= 1) d += __shfl_xor_sync(0xffffffffu, d, o);

        if (lane == 0) {
            float u = u01(rbits32(0u, 7u, (uint32_t)r));   // key(7)
            float sc = d + (-logf(-logf(u)));
            g_scores[r] = sc;
            if (r < n_score_out) out[r] = sc;
            atomicAdd(&g_hist[score_key(sc) >> (32 - HBITS)], 1);
        }
    }
    gbar();

    // ---- J1: warp-per-chunk hist partial sums (1024 chunks x 128 bins) ----
    for (int c = gwarp; c < 1024; c += nwarps) {
        int sum = 0;
#pragma unroll
        for (int k = 0; k < 4; k++) sum += __ldcg(&g_hist[c * 128 + k * 32 + lane]);
#pragma unroll
        for (int o = 16; o; o >>= 1) sum += __shfl_xor_sync(0xffffffffu, sum, o);
        if (lane == 0) g_chunkSum[c] = sum;
    }
    gbar();

    // ---- J2: block 0 finds threshold digit ----
    if (bb == 0) {
        for (int i = t; i < 1024; i += TPB) sm_i[i] = __ldcg(&g_chunkSum[i]);
        if (t == 0) sm_small[9] = -1;
        __syncthreads();
        // per-thread group of 4 chunks; suffix sums via block scan
        int ps = sm_i[t * 4] + sm_i[t * 4 + 1] + sm_i[t * 4 + 2] + sm_i[t * 4 + 3];
        int x2 = ps;
#pragma unroll
        for (int o = 1; o < 32; o <<= 1) { int y = __shfl_up_sync(0xffffffffu, x2, o); if (lane >= o) x2 += y; }
        if (lane == 31) sm_small[t >> 5] = x2;
        __syncthreads();
        if (t == 0) { int run = 0; for (int i = 0; i < 8; i++) { int v = sm_small[i]; sm_small[i] = run; run += v; } sm_small[8] = run; }
        __syncthreads();
        int inclP = x2 + sm_small[t >> 5];
        int total = sm_small[8];
        int suffixGroup = total - (inclP - ps);   // sum of chunks >= t*4
        // find cc = max chunk with suffix >= KTOP
        {
            int run = suffixGroup;
            for (int i = 0; i < 4; i++) {
                int c = t * 4 + i;
                if (run >= KTOP) atomicMax(&sm_small[9], c);
                run -= sm_i[c];
            }
        }
        __syncthreads();
        int cc = sm_small[9];
        // recompute S[cc]
        {
            int run = suffixGroup;
            for (int i = 0; i < 4; i++) {
                int c = t * 4 + i;
                if (c == cc) sm_small[10] = run;
                run -= sm_i[c];
            }
        }
        __syncthreads();
        if (t < 128) sm_i[4096 + t] = __ldcg(&g_hist[cc * 128 + t]);
        __syncthreads();
        if (t == 0) {
            int cum = sm_small[10] - sm_i[cc];   // sum of chunks strictly above cc... wait: S[cc] - chunkSum[cc]
            // cum = everything above chunk cc; walk bins high->low
            int digit = cc * 128;
            for (int bbin = 127; bbin >= 0; bbin--) {
                int h = sm_i[4096 + bbin];
                if (cum + h >= KTOP) { digit = cc * 128 + bbin; break; }
                cum += h;
            }
            g_sel_digit = digit;
        }
    }
    gbar();

    // ---- K: compact candidates ----
    {
        int sd = __ldcg(&g_sel_digit);
        for (int i = gtid; i < NN; i += nthreads) {
            uint32_t k = score_key(__ldcg(&g_scores[i]));
            if ((int)(k >> (32 - HBITS)) >= sd) {
                int p = atomicAdd(&g_cand_cnt, 1);
                if (p < CAP) { g_cand_key[p] = k; g_cand_idx[p] = i; }
            }
        }
    }
    gbar();

    // ---- L: block 0 sorts candidates (bitonic) and writes top-k ----
    if (bb == 0) {
        int n = __ldcg(&g_cand_cnt); if (n > CAP) n = CAP;
        int m = KTOP; while (m < n) m <<= 1;
        for (int i = t; i < m; i += TPB) {
            sm_sort[i] = (i < n)
                ? ((((unsigned long long)__ldcg(&g_cand_key[i])) << 32) |
                   (uint32_t)(~(uint32_t)__ldcg(&g_cand_idx[i])))
                : 0ull;
        }
        __syncthreads();
        for (int size = 2; size <= m; size <<= 1) {
            for (int stride = size >> 1; stride > 0; stride >>= 1) {
                for (int i = t; i < m / 2; i += TPB) {
                    int lo = 2 * i - (i & (stride - 1));
                    int hi = lo + stride;
                    bool desc = ((lo & size) == 0);
                    unsigned long long a = sm_sort[lo], b2 = sm_sort[hi];
                    bool sw = desc ? (a < b2) : (a > b2);
                    if (sw) { sm_sort[lo] = b2; sm_sort[hi] = a; }
                }
                __syncthreads();
            }
        }
        for (int j = t; j < KTOP; j += TPB) {
            uint32_t idx = ~(uint32_t)(sm_sort[j] & 0xffffffffull);
            if (out_size >= NN + KTOP) out[NN + j] = (float)idx;
            else if (out_size == KTOP) ((int*)out)[j] = (int)idx;
        }
    }
}

// ---------------- launch ----------------
extern "C" void kernel_launch(void* const* d_in, const int* in_sizes, int n_in,
                              void* d_out, int out_size) {
    const int* rows = (const int*)d_in[0];       // edge_index[0]
    const int* cols = rows + EE;                 // edge_index[1]
    const float* adj = (const float*)d_in[1];
    const float* embeds = (const float*)d_in[2];
    float* out = (float*)d_out;
    (void)in_sizes; (void)n_in;

    // fold_in(key(42), i): threefry((0,42),(0,i)) -> derived key
    uint32_t fk[3][2];
    for (uint32_t i = 0; i < 3; i++) tf2x32(0u, 42u, 0u, i, fk[i][0], fk[i][1]);

    // grid sized for guaranteed co-residency (software grid barrier)
    int dev = 0; cudaGetDevice(&dev);
    int nsm = 0; cudaDeviceGetAttribute(&nsm, cudaDevAttrMultiProcessorCount, dev);
    int bpm = 0;
    cudaOccupancyMaxActiveBlocksPerMultiprocessor(&bpm, mega_kernel, TPB, 0);
    int B = nsm * bpm;
    if (B < 1) B = 1;
    if (B > 2048) B = 2048;

    int n_score_out = (out_size == KTOP) ? 0 : ((out_size < NN) ? out_size : NN);
    mega_kernel<<<B, TPB>>>(rows, cols, adj, embeds, out, out_size, n_score_out,
                            fk[0][0], fk[0][1], fk[1][0], fk[1][1], fk[2][0], fk[2][1]);
}